// round 8
// baseline (speedup 1.0000x reference)
#include <cuda_runtime.h>
#include <cstdint>

// InversePoseMatrixLayer: out = [R^T | -R^T t] for 4M poses (3x4 fp32 each).
//
// R7 = R6 resubmitted after infra failure (container died; kernel never ran).
// Persistent grid + double-buffered TMA pipeline (2 x 480-pose = 2 x 22.5KB
// buffers, 45KB static smem < 48KB cap) + L2 evict-first hints on both bulk
// directions. All global traffic via cp.async.bulk: zero per-thread global
// wavefronts; threads only do the in-place smem transform (conflict-free
// stride-3-float4 bank pattern).

#define THREADS         256
#define POSES_PER_TILE  480
#define TILE_F4         (POSES_PER_TILE * 3)     // 1440 float4 = 22.5KB
#define GRID_CTAS       592                      // persistent-loop stride

__device__ __forceinline__ uint32_t smem_u32(const void* p) {
    uint32_t a;
    asm("{ .reg .u64 t; cvta.to.shared.u64 t, %1; cvt.u32.u64 %0, t; }"
        : "=r"(a) : "l"(p));
    return a;
}

__device__ __forceinline__ void invert_pose_inplace(float4* s, int slot) {
    const float4 r0 = s[slot + 0];   // (R00, R01, R02, t0)
    const float4 r1 = s[slot + 1];   // (R10, R11, R12, t1)
    const float4 r2 = s[slot + 2];   // (R20, R21, R22, t2)

    const float ti0 = -(r0.x * r0.w + r1.x * r1.w + r2.x * r2.w);
    const float ti1 = -(r0.y * r0.w + r1.y * r1.w + r2.y * r2.w);
    const float ti2 = -(r0.z * r0.w + r1.z * r1.w + r2.z * r2.w);

    s[slot + 0] = make_float4(r0.x, r1.x, r2.x, ti0);
    s[slot + 1] = make_float4(r0.y, r1.y, r2.y, ti1);
    s[slot + 2] = make_float4(r0.z, r1.z, r2.z, ti2);
}

__device__ __forceinline__ void mbar_wait(uint32_t mbar, uint32_t parity) {
    uint32_t done;
    asm volatile(
        "{\n\t"
        ".reg .pred p;\n\t"
        "mbarrier.try_wait.parity.shared.b64 p, [%1], %2;\n\t"
        "selp.b32 %0, 1, 0, p;\n\t"
        "}"
        : "=r"(done) : "r"(mbar), "r"(parity) : "memory");
    while (!done) {
        asm volatile(
            "{\n\t"
            ".reg .pred p;\n\t"
            "mbarrier.try_wait.parity.shared.b64 p, [%1], %2, 0x989680;\n\t"
            "selp.b32 %0, 1, 0, p;\n\t"
            "}"
            : "=r"(done) : "r"(mbar), "r"(parity) : "memory");
    }
}

__global__ __launch_bounds__(THREADS) void inverse_pose_kernel(
    const char* __restrict__ in, char* __restrict__ out,
    int n_poses, int n_tiles)
{
    __shared__ __align__(128) float4 tile[2][TILE_F4];
    __shared__ __align__(8) uint64_t mbar[2];

    const int tid = threadIdx.x;
    const uint32_t s_tile0 = smem_u32(&tile[0][0]);
    const uint32_t s_tile1 = smem_u32(&tile[1][0]);
    const uint32_t s_mbar0 = smem_u32(&mbar[0]);
    const uint32_t s_mbar1 = smem_u32(&mbar[1]);

    uint64_t pol;
    asm volatile("createpolicy.fractional.L2::evict_first.b64 %0, 1.0;" : "=l"(pol));

    if (tid == 0) {
        asm volatile("mbarrier.init.shared.b64 [%0], %1;" :: "r"(s_mbar0), "r"(1u) : "memory");
        asm volatile("mbarrier.init.shared.b64 [%0], %1;" :: "r"(s_mbar1), "r"(1u) : "memory");
    }
    __syncthreads();

    uint32_t phase[2] = {0u, 0u};
    int iter = 0;

    for (int t = blockIdx.x; t < n_tiles; t += GRID_CTAS, iter++) {
        const int b = iter & 1;
        const uint32_t s_buf = b ? s_tile1 : s_tile0;
        const uint32_t s_mb  = b ? s_mbar1 : s_mbar0;
        float4* buf = &tile[b][0];

        const long long pose_base = (long long)t * POSES_PER_TILE;
        int poses_here = n_poses - (int)pose_base;
        if (poses_here > POSES_PER_TILE) poses_here = POSES_PER_TILE;
        const unsigned bytes = (unsigned)poses_here * 48u;

        if (tid == 0) {
            // Ensure the TMA store that last read this buffer has finished
            // reading before the new load overwrites it (<=1 store pending).
            asm volatile("cp.async.bulk.wait_group.read 1;" ::: "memory");
            asm volatile("mbarrier.arrive.expect_tx.shared.b64 _, [%0], %1;"
                         :: "r"(s_mb), "r"(bytes) : "memory");
            asm volatile(
                "cp.async.bulk.shared::cta.global.mbarrier::complete_tx::bytes.L2::cache_hint "
                "[%0], [%1], %2, [%3], %4;"
                :: "r"(s_buf), "l"(in + pose_base * 48), "r"(bytes),
                   "r"(s_mb), "l"(pol)
                : "memory");
        }

        mbar_wait(s_mb, phase[b]);
        phase[b] ^= 1u;

        // Two poses per thread, interleaved by 256: both access sets keep the
        // conflict-free stride-3-float4 smem bank pattern.
        if (tid < poses_here)
            invert_pose_inplace(buf, 3 * tid);
        const int p2 = tid + 256;
        if (p2 < poses_here)
            invert_pose_inplace(buf, 3 * p2);

        asm volatile("fence.proxy.async.shared::cta;" ::: "memory");
        __syncthreads();

        if (tid == 0) {
            asm volatile(
                "cp.async.bulk.global.shared::cta.bulk_group.L2::cache_hint "
                "[%0], [%1], %2, %3;"
                :: "l"(out + pose_base * 48), "r"(s_buf), "r"(bytes), "l"(pol)
                : "memory");
            asm volatile("cp.async.bulk.commit_group;" ::: "memory");
        }
    }

    // Keep the CTA (and its smem) alive until all TMA stores have read smem.
    if (tid == 0)
        asm volatile("cp.async.bulk.wait_group.read 0;" ::: "memory");
}

extern "C" void kernel_launch(void* const* d_in, const int* in_sizes, int n_in,
                              void* d_out, int out_size)
{
    const char* in = (const char*)d_in[0];
    char* out = (char*)d_out;
    const int n_poses = in_sizes[0] / 12;   // 12 floats per pose
    const int n_tiles = (n_poses + POSES_PER_TILE - 1) / POSES_PER_TILE;

    const int blocks = n_tiles < GRID_CTAS ? n_tiles : GRID_CTAS;
    inverse_pose_kernel<<<blocks, THREADS>>>(in, out, n_poses, n_tiles);
}

// round 9
// speedup vs baseline: 1.1333x; 1.1333x over previous
#include <cuda_runtime.h>

// InversePoseMatrixLayer: out = [R^T | -R^T t] for 4M poses (3x4 fp32 each).
//
// R8: revert to the best-e2e structure (R1: simple grid, smem-staging
// transpose, full occupancy) and add the one untested DRAM-path lever:
// streaming (evict-first) cache hints on all global loads/stores. 384MB
// streams through L2 exactly once -- don't let it thrash evict-normal lines.

#define POSES_PER_BLOCK 256
#define VEC_PER_BLOCK   (POSES_PER_BLOCK * 3)   // float4s per block

__global__ __launch_bounds__(POSES_PER_BLOCK) void inverse_pose_kernel(
    const float4* __restrict__ in, float4* __restrict__ out, int n_poses)
{
    __shared__ float4 s[VEC_PER_BLOCK];

    const int tid      = threadIdx.x;
    const int vec_base = blockIdx.x * VEC_PER_BLOCK;   // float4 index of block start
    const int n_vec    = n_poses * 3;

    // Phase 1: coalesced global -> smem (unit stride, streaming loads)
    #pragma unroll
    for (int k = 0; k < 3; k++) {
        int idx = vec_base + k * POSES_PER_BLOCK + tid;
        if (idx < n_vec)
            s[k * POSES_PER_BLOCK + tid] = __ldcs(&in[idx]);
    }
    __syncthreads();

    // Phase 2: per-thread pose inverse in smem-local slots.
    // Thread i reads/writes only slots {3i, 3i+1, 3i+2} -> no race.
    // stride-3-float4 smem pattern is bank-conflict-free.
    const int p = blockIdx.x * POSES_PER_BLOCK + tid;
    if (p < n_poses) {
        const float4 r0 = s[3 * tid + 0];   // (R00, R01, R02, t0)
        const float4 r1 = s[3 * tid + 1];   // (R10, R11, R12, t1)
        const float4 r2 = s[3 * tid + 2];   // (R20, R21, R22, t2)

        const float ti0 = -(r0.x * r0.w + r1.x * r1.w + r2.x * r2.w);
        const float ti1 = -(r0.y * r0.w + r1.y * r1.w + r2.y * r2.w);
        const float ti2 = -(r0.z * r0.w + r1.z * r1.w + r2.z * r2.w);

        s[3 * tid + 0] = make_float4(r0.x, r1.x, r2.x, ti0);
        s[3 * tid + 1] = make_float4(r0.y, r1.y, r2.y, ti1);
        s[3 * tid + 2] = make_float4(r0.z, r1.z, r2.z, ti2);
    }
    __syncthreads();

    // Phase 3: coalesced smem -> global (unit stride, streaming stores)
    #pragma unroll
    for (int k = 0; k < 3; k++) {
        int idx = vec_base + k * POSES_PER_BLOCK + tid;
        if (idx < n_vec)
            __stcs(&out[idx], s[k * POSES_PER_BLOCK + tid]);
    }
}

extern "C" void kernel_launch(void* const* d_in, const int* in_sizes, int n_in,
                              void* d_out, int out_size)
{
    const float4* in = (const float4*)d_in[0];
    float4* out = (float4*)d_out;
    const int n_poses = in_sizes[0] / 12;   // 12 floats per pose

    const int blocks = (n_poses + POSES_PER_BLOCK - 1) / POSES_PER_BLOCK;
    inverse_pose_kernel<<<blocks, POSES_PER_BLOCK>>>(in, out, n_poses);
}